// round 2
// baseline (speedup 1.0000x reference)
#include <cuda_runtime.h>

#define NUSER 100000
#define NITEM 100000

// ---------------- scratch (device globals; allocation-free) ----------------
__device__ float4 g_Wh_uu[NUSER * 32];   // [NU,128] projected feats
__device__ float4 g_Wh_ui[NUSER * 32];
__device__ float4 g_Wh_iu[NITEM * 32];
__device__ float4 g_acc_uu[NUSER * 32];  // segment sums
__device__ float4 g_acc_iu[NUSER * 32];
__device__ float4 g_acc_ui[NITEM * 32];
__device__ float4 g_h_user[NUSER * 32];  // layer-0 outputs (post relu)
__device__ float4 g_h_item[NITEM * 32];
__device__ float4 g_Wh1_uu[NUSER * 4];   // [NU,16]
__device__ float4 g_Wh1_iu[NITEM * 4];
__device__ float4 g_acc1_uu[NUSER * 4];
__device__ float4 g_acc1_iu[NUSER * 4];
__device__ float  g_deg_uu[NUSER];
__device__ float  g_deg_iu[NUSER];
__device__ float  g_deg_ui[NITEM];

// ---------------- zero all accumulators ----------------
__global__ void zero_all() {
    int i = blockIdx.x * blockDim.x + threadIdx.x;
    float4 z = make_float4(0.f, 0.f, 0.f, 0.f);
    if (i < NUSER * 32) { g_acc_uu[i] = z; g_acc_iu[i] = z; }
    if (i < NITEM * 32) { g_acc_ui[i] = z; }
    if (i < NUSER * 4)  { g_acc1_uu[i] = z; g_acc1_iu[i] = z; }
    if (i < NUSER)      { g_deg_uu[i] = 0.f; g_deg_iu[i] = 0.f; }
    if (i < NITEM)      { g_deg_ui[i] = 0.f; }
}

// ---------------- GEMM: Y[M,128] = X[M,128] @ W[128,128] + b ----------------
// 128x128 block tile, BK=8, 256 threads, 8x8 micro-tile per thread.
__global__ void gemm128(const float* __restrict__ X, const float* __restrict__ W,
                        const float* __restrict__ b, int M, int which) {
    float* Y = (which == 0) ? (float*)g_Wh_uu
             : (which == 1) ? (float*)g_Wh_ui
                            : (float*)g_Wh_iu;
    __shared__ float As[8][128];
    __shared__ float Bs[8][128];
    const int tid = threadIdx.x;
    const int bm = blockIdx.x * 128;
    const int tx = tid & 15;        // n-tile 0..15
    const int ty = tid >> 4;        // m-tile 0..15
    const int a_m = tid >> 1;       // 0..127
    const int a_k = (tid & 1) * 4;  // 0 or 4
    const int b_k = tid >> 5;       // 0..7
    const int b_n = (tid & 31) * 4; // 0..124
    const int rowA = bm + a_m;

    float acc[8][8];
#pragma unroll
    for (int i = 0; i < 8; i++)
#pragma unroll
        for (int j = 0; j < 8; j++) acc[i][j] = 0.f;

    for (int k0 = 0; k0 < 128; k0 += 8) {
        float4 av = make_float4(0.f, 0.f, 0.f, 0.f);
        if (rowA < M) av = *(const float4*)(X + (size_t)rowA * 128 + k0 + a_k);
        As[a_k + 0][a_m] = av.x; As[a_k + 1][a_m] = av.y;
        As[a_k + 2][a_m] = av.z; As[a_k + 3][a_m] = av.w;
        *(float4*)&Bs[b_k][b_n] = *(const float4*)(W + (size_t)(k0 + b_k) * 128 + b_n);
        __syncthreads();
#pragma unroll
        for (int k = 0; k < 8; k++) {
            float4 a0 = *(float4*)&As[k][ty * 8];
            float4 a1 = *(float4*)&As[k][ty * 8 + 4];
            float4 b0 = *(float4*)&Bs[k][tx * 8];
            float4 b1 = *(float4*)&Bs[k][tx * 8 + 4];
            float ar[8] = {a0.x, a0.y, a0.z, a0.w, a1.x, a1.y, a1.z, a1.w};
            float br[8] = {b0.x, b0.y, b0.z, b0.w, b1.x, b1.y, b1.z, b1.w};
#pragma unroll
            for (int i = 0; i < 8; i++)
#pragma unroll
                for (int j = 0; j < 8; j++)
                    acc[i][j] = fmaf(ar[i], br[j], acc[i][j]);
        }
        __syncthreads();
    }
#pragma unroll
    for (int i = 0; i < 8; i++) {
        int row = bm + ty * 8 + i;
        if (row < M) {
#pragma unroll
            for (int j = 0; j < 8; j += 4) {
                int col = tx * 8 + j;
                float4 v;
                v.x = acc[i][j + 0] + b[col + 0];
                v.y = acc[i][j + 1] + b[col + 1];
                v.z = acc[i][j + 2] + b[col + 2];
                v.w = acc[i][j + 3] + b[col + 3];
                *(float4*)(Y + (size_t)row * 128 + col) = v;
            }
        }
    }
}

// ---------------- degree count ----------------
__global__ void degree_k(const int* __restrict__ dst, int ne, int which) {
    float* deg = (which == 0) ? g_deg_uu : (which == 1) ? g_deg_iu : g_deg_ui;
    int i = blockIdx.x * blockDim.x + threadIdx.x;
    if (i < ne) atomicAdd(&deg[dst[i]], 1.f);
}

// ---------------- edge scatter, 128-wide feats: warp per edge ----------------
__global__ void scatter128(const int* __restrict__ src, const int* __restrict__ dst,
                           int ne, int which) {
    const float4* Wh = (which == 0) ? g_Wh_uu : (which == 1) ? g_Wh_iu : g_Wh_ui;
    float* acc = (which == 0) ? (float*)g_acc_uu
               : (which == 1) ? (float*)g_acc_iu
                              : (float*)g_acc_ui;
    int w = (blockIdx.x * blockDim.x + threadIdx.x) >> 5;
    int lane = threadIdx.x & 31;
    if (w >= ne) return;
    int s = src[w], d = dst[w];
    float4 v = Wh[(size_t)s * 32 + lane];
    float* p = acc + (size_t)d * 128 + lane * 4;
    atomicAdd(p + 0, v.x);
    atomicAdd(p + 1, v.y);
    atomicAdd(p + 2, v.z);
    atomicAdd(p + 3, v.w);
}

// ---------------- layer-0 combine: mean + mean, relu ----------------
__global__ void finalize_user() {
    int i = blockIdx.x * blockDim.x + threadIdx.x;
    if (i >= NUSER * 32) return;
    int node = i >> 5;
    float iu = 1.f / fmaxf(g_deg_uu[node], 1.f);
    float ii = 1.f / fmaxf(g_deg_iu[node], 1.f);
    float4 a = g_acc_uu[i], c = g_acc_iu[i];
    float4 h;
    h.x = fmaxf(a.x * iu + c.x * ii, 0.f);
    h.y = fmaxf(a.y * iu + c.y * ii, 0.f);
    h.z = fmaxf(a.z * iu + c.z * ii, 0.f);
    h.w = fmaxf(a.w * iu + c.w * ii, 0.f);
    g_h_user[i] = h;
}

__global__ void finalize_item() {
    int i = blockIdx.x * blockDim.x + threadIdx.x;
    if (i >= NITEM * 32) return;
    int node = i >> 5;
    float inv = 1.f / fmaxf(g_deg_ui[node], 1.f);
    float4 a = g_acc_ui[i];
    float4 h;
    h.x = fmaxf(a.x * inv, 0.f);
    h.y = fmaxf(a.y * inv, 0.f);
    h.z = fmaxf(a.z * inv, 0.f);
    h.w = fmaxf(a.w * inv, 0.f);
    g_h_item[i] = h;
}

// ---------------- skinny GEMM: Y[M,16] = X[M,128] @ W[128,16] + b ----------------
// 64 rows per block, 256 threads; X tile staged in smem (pitch 130 to dodge conflicts).
__global__ void gemm16(const float* __restrict__ W, const float* __restrict__ b,
                       int M, int which) {
    const float* X = (which == 0) ? (const float*)g_h_user : (const float*)g_h_item;
    float* Y = (which == 0) ? (float*)g_Wh1_uu : (float*)g_Wh1_iu;
    __shared__ float Xs[64][130];
    __shared__ float Ws[128 * 16];
    __shared__ float bs[16];
    int tid = threadIdx.x;
    int base = blockIdx.x * 64;
#pragma unroll
    for (int i = 0; i < 8; i++) Ws[tid + i * 256] = W[tid + i * 256];
    if (tid < 16) bs[tid] = b[tid];
#pragma unroll
    for (int i = 0; i < 8; i++) {
        int f = tid + i * 256;        // float4 index within 64x128 tile
        int r = f >> 5, c4 = f & 31;
        int row = base + r;
        float4 v = make_float4(0.f, 0.f, 0.f, 0.f);
        if (row < M) v = *(const float4*)(X + (size_t)row * 128 + c4 * 4);
        Xs[r][c4 * 4 + 0] = v.x; Xs[r][c4 * 4 + 1] = v.y;
        Xs[r][c4 * 4 + 2] = v.z; Xs[r][c4 * 4 + 3] = v.w;
    }
    __syncthreads();
    int r = tid >> 2, cb = (tid & 3) * 4;
    float4 acc = make_float4(0.f, 0.f, 0.f, 0.f);
#pragma unroll 8
    for (int k = 0; k < 128; k++) {
        float x = Xs[r][k];
        float4 w = *(float4*)&Ws[k * 16 + cb];
        acc.x = fmaf(x, w.x, acc.x);
        acc.y = fmaf(x, w.y, acc.y);
        acc.z = fmaf(x, w.z, acc.z);
        acc.w = fmaf(x, w.w, acc.w);
    }
    int row = base + r;
    if (row < M) {
        float4 o;
        o.x = acc.x + bs[cb + 0];
        o.y = acc.y + bs[cb + 1];
        o.z = acc.z + bs[cb + 2];
        o.w = acc.w + bs[cb + 3];
        *(float4*)(Y + (size_t)row * 16 + cb) = o;
    }
}

// ---------------- edge scatter, 16-wide feats: 4 threads per edge ----------------
__global__ void scatter16(const int* __restrict__ src, const int* __restrict__ dst,
                          int ne, int which) {
    const float4* Wh = (which == 0) ? g_Wh1_uu : g_Wh1_iu;
    float* acc = (which == 0) ? (float*)g_acc1_uu : (float*)g_acc1_iu;
    int id = blockIdx.x * blockDim.x + threadIdx.x;
    int e = id >> 2, part = id & 3;
    if (e >= ne) return;
    int s = src[e], d = dst[e];
    float4 v = Wh[(size_t)s * 4 + part];
    float* p = acc + (size_t)d * 16 + part * 4;
    atomicAdd(p + 0, v.x);
    atomicAdd(p + 1, v.y);
    atomicAdd(p + 2, v.z);
    atomicAdd(p + 3, v.w);
}

// ---------------- final combine: mean + mean (no relu) ----------------
__global__ void final_out(float4* __restrict__ out) {
    int i = blockIdx.x * blockDim.x + threadIdx.x;
    if (i >= NUSER * 4) return;
    int node = i >> 2;
    float iu = 1.f / fmaxf(g_deg_uu[node], 1.f);
    float ii = 1.f / fmaxf(g_deg_iu[node], 1.f);
    float4 a = g_acc1_uu[i], c = g_acc1_iu[i];
    float4 o;
    o.x = a.x * iu + c.x * ii;
    o.y = a.y * iu + c.y * ii;
    o.z = a.z * iu + c.z * ii;
    o.w = a.w * iu + c.w * ii;
    out[i] = o;
}

// ---------------- launch ----------------
extern "C" void kernel_launch(void* const* d_in, const int* in_sizes, int n_in,
                              void* d_out, int out_size) {
    const float* embed_user = (const float*)d_in[0];
    const float* embed_item = (const float*)d_in[1];
    const int* src_uu = (const int*)d_in[2];
    const int* dst_uu = (const int*)d_in[3];
    const int* src_ui = (const int*)d_in[4];
    const int* dst_ui = (const int*)d_in[5];
    const int* src_iu = (const int*)d_in[6];
    const int* dst_iu = (const int*)d_in[7];
    const float* W0_uu = (const float*)d_in[8];
    const float* b0_uu = (const float*)d_in[9];
    const float* W0_ui = (const float*)d_in[10];
    const float* b0_ui = (const float*)d_in[11];
    const float* W0_iu = (const float*)d_in[12];
    const float* b0_iu = (const float*)d_in[13];
    const float* W1_uu = (const float*)d_in[14];
    const float* b1_uu = (const float*)d_in[15];
    const float* W1_iu = (const float*)d_in[18];
    const float* b1_iu = (const float*)d_in[19];
    const int ne = in_sizes[2];

    // zero accumulators + degrees
    zero_all<<<(NUSER * 32 + 255) / 256, 256>>>();

    // layer-0 projections
    gemm128<<<(NUSER + 127) / 128, 256>>>(embed_user, W0_uu, b0_uu, NUSER, 0);
    gemm128<<<(NUSER + 127) / 128, 256>>>(embed_user, W0_ui, b0_ui, NUSER, 1);
    gemm128<<<(NITEM + 127) / 128, 256>>>(embed_item, W0_iu, b0_iu, NITEM, 2);

    // degrees (shared by both layers)
    degree_k<<<(ne + 255) / 256, 256>>>(dst_uu, ne, 0);
    degree_k<<<(ne + 255) / 256, 256>>>(dst_iu, ne, 1);
    degree_k<<<(ne + 255) / 256, 256>>>(dst_ui, ne, 2);

    // layer-0 aggregation (warp per edge), one etype at a time to keep L2 warm
    int sblocks = (int)(((long long)ne * 32 + 255) / 256);
    scatter128<<<sblocks, 256>>>(src_uu, dst_uu, ne, 0);
    scatter128<<<sblocks, 256>>>(src_iu, dst_iu, ne, 1);
    scatter128<<<sblocks, 256>>>(src_ui, dst_ui, ne, 2);

    // combine + relu
    finalize_user<<<(NUSER * 32 + 255) / 256, 256>>>();
    finalize_item<<<(NITEM * 32 + 255) / 256, 256>>>();

    // layer-1 projections
    gemm16<<<(NUSER + 63) / 64, 256>>>(W1_uu, b1_uu, NUSER, 0);
    gemm16<<<(NITEM + 63) / 64, 256>>>(W1_iu, b1_iu, NITEM, 1);

    // layer-1 aggregation
    int s16blocks = (int)(((long long)ne * 4 + 255) / 256);
    scatter16<<<s16blocks, 256>>>(src_uu, dst_uu, ne, 0);
    scatter16<<<s16blocks, 256>>>(src_iu, dst_iu, ne, 1);

    // output
    final_out<<<(NUSER * 4 + 255) / 256, 256>>>((float4*)d_out);
}

// round 3
// speedup vs baseline: 1.4547x; 1.4547x over previous
#include <cuda_runtime.h>

#define NUSER 100000
#define NITEM 100000

// ---------------- scratch (device globals; allocation-free) ----------------
__device__ float4 g_Wh_uu[NUSER * 32];   // [NU,128] projected feats
__device__ float4 g_Wh_ui[NUSER * 32];
__device__ float4 g_Wh_iu[NITEM * 32];
__device__ float4 g_acc_uu[NUSER * 32];  // segment sums (layer 0)
__device__ float4 g_acc_iu[NUSER * 32];
__device__ float4 g_acc_ui[NITEM * 32];
__device__ float4 g_Wh1_uu[NUSER * 4];   // [NU,16]
__device__ float4 g_Wh1_iu[NITEM * 4];
__device__ float4 g_acc1_uu[NUSER * 4];
__device__ float4 g_acc1_iu[NUSER * 4];
__device__ float  g_deg_uu[NUSER];
__device__ float  g_deg_iu[NUSER];
__device__ float  g_deg_ui[NITEM];

// vector fp32 reduction (sm_90+): one 16B L2 atomic instead of 4 scalar ones
__device__ __forceinline__ void red4(float* p, float4 v) {
    asm volatile("red.global.add.v4.f32 [%0], {%1, %2, %3, %4};"
                 :: "l"(p), "f"(v.x), "f"(v.y), "f"(v.z), "f"(v.w)
                 : "memory");
}

// ---------------- zero all accumulators ----------------
__global__ void zero_all() {
    int i = blockIdx.x * blockDim.x + threadIdx.x;
    float4 z = make_float4(0.f, 0.f, 0.f, 0.f);
    if (i < NUSER * 32) { g_acc_uu[i] = z; g_acc_iu[i] = z; }
    if (i < NITEM * 32) { g_acc_ui[i] = z; }
    if (i < NUSER * 4)  { g_acc1_uu[i] = z; g_acc1_iu[i] = z; }
    if (i < NUSER)      { g_deg_uu[i] = 0.f; g_deg_iu[i] = 0.f; }
    if (i < NITEM)      { g_deg_ui[i] = 0.f; }
}

// ---------------- GEMM: Y[M,128] = X[M,128] @ W[128,128] + b ----------------
// 128x128 block tile, BK=8, 256 threads, 8x8 micro-tile, double-buffered smem.
__global__ void gemm128(const float* __restrict__ X, const float* __restrict__ W,
                        const float* __restrict__ b, int M, int which) {
    float* Y = (which == 0) ? (float*)g_Wh_uu
             : (which == 1) ? (float*)g_Wh_ui
                            : (float*)g_Wh_iu;
    __shared__ float As[2][8][128];
    __shared__ float Bs[2][8][128];
    const int tid = threadIdx.x;
    const int bm = blockIdx.x * 128;
    const int tx = tid & 15;        // n-tile 0..15
    const int ty = tid >> 4;        // m-tile 0..15
    const int a_m = tid >> 1;       // 0..127
    const int a_k = (tid & 1) * 4;  // 0 or 4
    const int b_k = tid >> 5;       // 0..7
    const int b_n = (tid & 31) * 4; // 0..124
    const int rowA = bm + a_m;
    const bool a_ok = rowA < M;

    float acc[8][8];
#pragma unroll
    for (int i = 0; i < 8; i++)
#pragma unroll
        for (int j = 0; j < 8; j++) acc[i][j] = 0.f;

    // preload tile 0
    float4 av = make_float4(0.f, 0.f, 0.f, 0.f);
    if (a_ok) av = *(const float4*)(X + (size_t)rowA * 128 + a_k);
    float4 bv = *(const float4*)(W + (size_t)b_k * 128 + b_n);
    As[0][a_k + 0][a_m] = av.x; As[0][a_k + 1][a_m] = av.y;
    As[0][a_k + 2][a_m] = av.z; As[0][a_k + 3][a_m] = av.w;
    *(float4*)&Bs[0][b_k][b_n] = bv;
    __syncthreads();

    int cur = 0;
    for (int k0 = 8; k0 <= 128; k0 += 8) {
        // prefetch next tile into registers
        if (k0 < 128) {
            av = make_float4(0.f, 0.f, 0.f, 0.f);
            if (a_ok) av = *(const float4*)(X + (size_t)rowA * 128 + k0 + a_k);
            bv = *(const float4*)(W + (size_t)(k0 + b_k) * 128 + b_n);
        }
        // compute from current buffer
#pragma unroll
        for (int k = 0; k < 8; k++) {
            float4 a0 = *(float4*)&As[cur][k][ty * 8];
            float4 a1 = *(float4*)&As[cur][k][ty * 8 + 4];
            float4 b0 = *(float4*)&Bs[cur][k][tx * 8];
            float4 b1 = *(float4*)&Bs[cur][k][tx * 8 + 4];
            float ar[8] = {a0.x, a0.y, a0.z, a0.w, a1.x, a1.y, a1.z, a1.w};
            float br[8] = {b0.x, b0.y, b0.z, b0.w, b1.x, b1.y, b1.z, b1.w};
#pragma unroll
            for (int i = 0; i < 8; i++)
#pragma unroll
                for (int j = 0; j < 8; j++)
                    acc[i][j] = fmaf(ar[i], br[j], acc[i][j]);
        }
        // stage next tile into alternate buffer
        if (k0 < 128) {
            int nxt = cur ^ 1;
            As[nxt][a_k + 0][a_m] = av.x; As[nxt][a_k + 1][a_m] = av.y;
            As[nxt][a_k + 2][a_m] = av.z; As[nxt][a_k + 3][a_m] = av.w;
            *(float4*)&Bs[nxt][b_k][b_n] = bv;
            __syncthreads();
            cur = nxt;
        }
    }
#pragma unroll
    for (int i = 0; i < 8; i++) {
        int row = bm + ty * 8 + i;
        if (row < M) {
#pragma unroll
            for (int j = 0; j < 8; j += 4) {
                int col = tx * 8 + j;
                float4 v;
                v.x = acc[i][j + 0] + b[col + 0];
                v.y = acc[i][j + 1] + b[col + 1];
                v.z = acc[i][j + 2] + b[col + 2];
                v.w = acc[i][j + 3] + b[col + 3];
                *(float4*)(Y + (size_t)row * 128 + col) = v;
            }
        }
    }
}

// ---------------- edge scatter, 128-wide feats: warp per edge ----------------
// Vector red.v4 + fused degree count (lane 0).
__global__ void scatter128(const int* __restrict__ src, const int* __restrict__ dst,
                           int ne, int which) {
    const float4* Wh = (which == 0) ? g_Wh_uu : (which == 1) ? g_Wh_iu : g_Wh_ui;
    float* acc = (which == 0) ? (float*)g_acc_uu
               : (which == 1) ? (float*)g_acc_iu
                              : (float*)g_acc_ui;
    float* deg = (which == 0) ? g_deg_uu : (which == 1) ? g_deg_iu : g_deg_ui;
    int w = (blockIdx.x * blockDim.x + threadIdx.x) >> 5;
    int lane = threadIdx.x & 31;
    if (w >= ne) return;
    int s = src[w], d = dst[w];
    float4 v = Wh[(size_t)s * 32 + lane];
    red4(acc + (size_t)d * 128 + lane * 4, v);
    if (lane == 0) atomicAdd(&deg[d], 1.f);
}

// ---------------- skinny GEMM with fused mean+relu epilogue-of-layer-0 ------
// Y[M,16] = relu(mean-combine(acc)) @ W[128,16] + b.  64 rows/block, 256 thr.
__global__ void gemm16(const float* __restrict__ W, const float* __restrict__ b,
                       int M, int which) {
    float* Y = (which == 0) ? (float*)g_Wh1_uu : (float*)g_Wh1_iu;
    __shared__ float Xs[64][130];
    __shared__ float Ws[128 * 16];
    __shared__ float bs[16];
    int tid = threadIdx.x;
    int base = blockIdx.x * 64;
#pragma unroll
    for (int i = 0; i < 8; i++) Ws[tid + i * 256] = W[tid + i * 256];
    if (tid < 16) bs[tid] = b[tid];
#pragma unroll
    for (int i = 0; i < 8; i++) {
        int f = tid + i * 256;        // float4 index within 64x128 tile
        int r = f >> 5, c4 = f & 31;
        int row = base + r;
        float4 v = make_float4(0.f, 0.f, 0.f, 0.f);
        if (row < M) {
            if (which == 0) {
                float iu = 1.f / fmaxf(g_deg_uu[row], 1.f);
                float ii = 1.f / fmaxf(g_deg_iu[row], 1.f);
                float4 a = g_acc_uu[(size_t)row * 32 + c4];
                float4 c = g_acc_iu[(size_t)row * 32 + c4];
                v.x = fmaxf(a.x * iu + c.x * ii, 0.f);
                v.y = fmaxf(a.y * iu + c.y * ii, 0.f);
                v.z = fmaxf(a.z * iu + c.z * ii, 0.f);
                v.w = fmaxf(a.w * iu + c.w * ii, 0.f);
            } else {
                float inv = 1.f / fmaxf(g_deg_ui[row], 1.f);
                float4 a = g_acc_ui[(size_t)row * 32 + c4];
                v.x = fmaxf(a.x * inv, 0.f);
                v.y = fmaxf(a.y * inv, 0.f);
                v.z = fmaxf(a.z * inv, 0.f);
                v.w = fmaxf(a.w * inv, 0.f);
            }
        }
        Xs[r][c4 * 4 + 0] = v.x; Xs[r][c4 * 4 + 1] = v.y;
        Xs[r][c4 * 4 + 2] = v.z; Xs[r][c4 * 4 + 3] = v.w;
    }
    __syncthreads();
    int r = tid >> 2, cb = (tid & 3) * 4;
    float4 acc = make_float4(0.f, 0.f, 0.f, 0.f);
#pragma unroll 8
    for (int k = 0; k < 128; k++) {
        float x = Xs[r][k];
        float4 w = *(float4*)&Ws[k * 16 + cb];
        acc.x = fmaf(x, w.x, acc.x);
        acc.y = fmaf(x, w.y, acc.y);
        acc.z = fmaf(x, w.z, acc.z);
        acc.w = fmaf(x, w.w, acc.w);
    }
    int row = base + r;
    if (row < M) {
        float4 o;
        o.x = acc.x + bs[cb + 0];
        o.y = acc.y + bs[cb + 1];
        o.z = acc.z + bs[cb + 2];
        o.w = acc.w + bs[cb + 3];
        *(float4*)(Y + (size_t)row * 16 + cb) = o;
    }
}

// ---------------- edge scatter, 16-wide feats: 4 threads per edge ----------------
__global__ void scatter16(const int* __restrict__ src, const int* __restrict__ dst,
                          int ne, int which) {
    const float4* Wh = (which == 0) ? g_Wh1_uu : g_Wh1_iu;
    float* acc = (which == 0) ? (float*)g_acc1_uu : (float*)g_acc1_iu;
    int id = blockIdx.x * blockDim.x + threadIdx.x;
    int e = id >> 2, part = id & 3;
    if (e >= ne) return;
    int s = src[e], d = dst[e];
    float4 v = Wh[(size_t)s * 4 + part];
    red4(acc + (size_t)d * 16 + part * 4, v);
}

// ---------------- final combine: mean + mean (no relu) ----------------
__global__ void final_out(float4* __restrict__ out) {
    int i = blockIdx.x * blockDim.x + threadIdx.x;
    if (i >= NUSER * 4) return;
    int node = i >> 2;
    float iu = 1.f / fmaxf(g_deg_uu[node], 1.f);
    float ii = 1.f / fmaxf(g_deg_iu[node], 1.f);
    float4 a = g_acc1_uu[i], c = g_acc1_iu[i];
    float4 o;
    o.x = a.x * iu + c.x * ii;
    o.y = a.y * iu + c.y * ii;
    o.z = a.z * iu + c.z * ii;
    o.w = a.w * iu + c.w * ii;
    out[i] = o;
}

// ---------------- launch ----------------
extern "C" void kernel_launch(void* const* d_in, const int* in_sizes, int n_in,
                              void* d_out, int out_size) {
    const float* embed_user = (const float*)d_in[0];
    const float* embed_item = (const float*)d_in[1];
    const int* src_uu = (const int*)d_in[2];
    const int* dst_uu = (const int*)d_in[3];
    const int* src_ui = (const int*)d_in[4];
    const int* dst_ui = (const int*)d_in[5];
    const int* src_iu = (const int*)d_in[6];
    const int* dst_iu = (const int*)d_in[7];
    const float* W0_uu = (const float*)d_in[8];
    const float* b0_uu = (const float*)d_in[9];
    const float* W0_ui = (const float*)d_in[10];
    const float* b0_ui = (const float*)d_in[11];
    const float* W0_iu = (const float*)d_in[12];
    const float* b0_iu = (const float*)d_in[13];
    const float* W1_uu = (const float*)d_in[14];
    const float* b1_uu = (const float*)d_in[15];
    const float* W1_iu = (const float*)d_in[18];
    const float* b1_iu = (const float*)d_in[19];
    const int ne = in_sizes[2];

    // zero accumulators + degrees
    zero_all<<<(NUSER * 32 + 255) / 256, 256>>>();

    // per-etype: project then scatter while Wh is L2-hot
    int sblocks = (int)(((long long)ne * 32 + 255) / 256);
    gemm128<<<(NUSER + 127) / 128, 256>>>(embed_user, W0_uu, b0_uu, NUSER, 0);
    scatter128<<<sblocks, 256>>>(src_uu, dst_uu, ne, 0);
    gemm128<<<(NITEM + 127) / 128, 256>>>(embed_item, W0_iu, b0_iu, NITEM, 2);
    scatter128<<<sblocks, 256>>>(src_iu, dst_iu, ne, 1);
    gemm128<<<(NUSER + 127) / 128, 256>>>(embed_user, W0_ui, b0_ui, NUSER, 1);
    scatter128<<<sblocks, 256>>>(src_ui, dst_ui, ne, 2);

    // layer-1 projections (mean+relu fused into X staging)
    gemm16<<<(NUSER + 63) / 64, 256>>>(W1_uu, b1_uu, NUSER, 0);
    gemm16<<<(NITEM + 63) / 64, 256>>>(W1_iu, b1_iu, NITEM, 1);

    // layer-1 aggregation
    int s16blocks = (int)(((long long)ne * 4 + 255) / 256);
    scatter16<<<s16blocks, 256>>>(src_uu, dst_uu, ne, 0);
    scatter16<<<s16blocks, 256>>>(src_iu, dst_iu, ne, 1);

    // output
    final_out<<<(NUSER * 4 + 255) / 256, 256>>>((float4*)d_out);
}

// round 5
// speedup vs baseline: 2.4783x; 1.7037x over previous
#include <cuda_runtime.h>
#include <cstdint>

#define NUSER 100000
#define NITEM 100000
#define NE    600000
#define NTOT  300000   // concatenated degree entries: [uu | iu | ui]

// ---------------- scratch (device globals; allocation-free) ----------------
__device__ float4 g_Wh_uu[NUSER * 32];   // [NU,128] projected feats
__device__ float4 g_Wh_ui[NUSER * 32];
__device__ float4 g_Wh_iu[NITEM * 32];
__device__ float4 g_acc_uu[NUSER * 32];  // segment sums (layer 0)
__device__ float4 g_acc_iu[NUSER * 32];
__device__ float4 g_acc_ui[NITEM * 32];
__device__ float4 g_Wh1_uu[NUSER * 4];   // [NU,16]
__device__ float4 g_Wh1_iu[NITEM * 4];
__device__ float4 g_acc1_uu[NUSER * 4];
__device__ float4 g_acc1_iu[NUSER * 4];
__device__ int    g_deg[NTOT];           // int degree, 3 etypes concatenated
__device__ int    g_incl[NTOT];          // inclusive scan scratch
__device__ int    g_rowstart[NTOT + 1];  // CSR row starts (global over 3 etypes)
__device__ int    g_cursor[NTOT];        // fill cursors
__device__ int    g_bsum[512];
__device__ int    g_bsum_ex[512];
__device__ int    g_slot[3 * NE];        // CSR column (src) array

// ---------------- helpers ----------------
__device__ __forceinline__ float tf32r(float x) {
    uint32_t u;
    asm("cvt.rna.tf32.f32 %0, %1;" : "=r"(u) : "f"(x));
    return __uint_as_float(u);
}

// ---------------- CSR build ----------------
__global__ void zero_deg() {
    int i = blockIdx.x * blockDim.x + threadIdx.x;
    if (i < NTOT) g_deg[i] = 0;
}

__global__ void hist_k(const int* __restrict__ dst, int off) {
    int i = blockIdx.x * blockDim.x + threadIdx.x;
    if (i < NE) atomicAdd(&g_deg[off + dst[i]], 1);
}

__global__ void scan_k1() {
    __shared__ int s[1024];
    int tid = threadIdx.x;
    int i = blockIdx.x * 1024 + tid;
    int v = (i < NTOT) ? g_deg[i] : 0;
    s[tid] = v;
    __syncthreads();
    for (int o = 1; o < 1024; o <<= 1) {
        int t = 0;
        if (tid >= o) t = s[tid - o];
        __syncthreads();
        s[tid] += t;
        __syncthreads();
    }
    if (i < NTOT) g_incl[i] = s[tid];
    if (tid == 1023) g_bsum[blockIdx.x] = s[1023];
}

__global__ void scan_k2(int nblk) {
    __shared__ int s[512];
    int tid = threadIdx.x;
    int v = (tid < nblk) ? g_bsum[tid] : 0;
    s[tid] = v;
    __syncthreads();
    for (int o = 1; o < 512; o <<= 1) {
        int t = 0;
        if (tid >= o) t = s[tid - o];
        __syncthreads();
        s[tid] += t;
        __syncthreads();
    }
    g_bsum_ex[tid] = s[tid] - v;   // exclusive
}

__global__ void scan_k3() {
    int i = blockIdx.x * 1024 + threadIdx.x;
    if (i >= NTOT) return;
    int d = g_deg[i];
    int ex = g_incl[i] - d + g_bsum_ex[i >> 10];
    g_rowstart[i] = ex;
    g_cursor[i] = ex;
    if (i == NTOT - 1) g_rowstart[NTOT] = ex + d;
}

__global__ void fill_k(const int* __restrict__ src, const int* __restrict__ dst, int off) {
    int i = blockIdx.x * blockDim.x + threadIdx.x;
    if (i >= NE) return;
    int pos = atomicAdd(&g_cursor[off + dst[i]], 1);
    g_slot[pos] = src[i];
}

// ---------------- TF32 tensor-core GEMM: Y[M,128] = X[M,128] @ W[128,128] + b
// 128x128 block tile, BK=16, 256 threads = 8 warps (4m x 2n), warp tile 32x64.
// mma.m16n8k8 tf32, double-buffered smem, one syncthreads per K-iter.
__global__ __launch_bounds__(256) void gemm128(
    const float* __restrict__ X, const float* __restrict__ W,
    const float* __restrict__ bias, int M, int which) {
    float* Y = (which == 0) ? (float*)g_Wh_uu
             : (which == 1) ? (float*)g_Wh_ui
                            : (float*)g_Wh_iu;
    __shared__ __align__(16) float Am[2][128][20];  // [m][k], pad 20 -> conflict-free frags
    __shared__ __align__(16) float Bs[2][16][136];  // [k][n], pad 136 -> conflict-free frags
    const int tid = threadIdx.x;
    const int lane = tid & 31;
    const int wid = tid >> 5;
    const int warp_m = wid & 3;        // 0..3 (32 rows each)
    const int warp_n = wid >> 2;       // 0..1 (64 cols each)
    const int bm = blockIdx.x * 128;
    const int g = lane >> 2;           // 0..7
    const int t = lane & 3;            // 0..3

    // staging indices: A tile 128x16 floats = 512 float4; B tile 16x128 = 512 float4
    const int fA0 = tid, fA1 = tid + 256;
    const int mA0 = fA0 >> 2, kqA0 = fA0 & 3;
    const int mA1 = fA1 >> 2, kqA1 = fA1 & 3;
    const int kB0 = fA0 >> 5, nB0 = (fA0 & 31) * 4;
    const int kB1 = fA1 >> 5, nB1 = (fA1 & 31) * 4;
    const int rowA0 = bm + mA0, rowA1 = bm + mA1;

    float c[2][8][4];
#pragma unroll
    for (int mt = 0; mt < 2; mt++)
#pragma unroll
        for (int nt = 0; nt < 8; nt++)
#pragma unroll
            for (int q = 0; q < 4; q++) c[mt][nt][q] = 0.f;

    float4 ra0, ra1, rb0, rb1;

#define LOAD_REGS(K0)                                                              \
    {                                                                              \
        ra0 = make_float4(0.f, 0.f, 0.f, 0.f);                                     \
        ra1 = make_float4(0.f, 0.f, 0.f, 0.f);                                     \
        if (rowA0 < M) ra0 = *(const float4*)(X + (size_t)rowA0 * 128 + (K0) + kqA0 * 4); \
        if (rowA1 < M) ra1 = *(const float4*)(X + (size_t)rowA1 * 128 + (K0) + kqA1 * 4); \
        rb0 = *(const float4*)(W + (size_t)((K0) + kB0) * 128 + nB0);              \
        rb1 = *(const float4*)(W + (size_t)((K0) + kB1) * 128 + nB1);              \
    }

#define STORE_BUF(B)                                                               \
    {                                                                              \
        float4 u;                                                                  \
        u.x = tf32r(ra0.x); u.y = tf32r(ra0.y); u.z = tf32r(ra0.z); u.w = tf32r(ra0.w); \
        *(float4*)&Am[B][mA0][kqA0 * 4] = u;                                       \
        u.x = tf32r(ra1.x); u.y = tf32r(ra1.y); u.z = tf32r(ra1.z); u.w = tf32r(ra1.w); \
        *(float4*)&Am[B][mA1][kqA1 * 4] = u;                                       \
        u.x = tf32r(rb0.x); u.y = tf32r(rb0.y); u.z = tf32r(rb0.z); u.w = tf32r(rb0.w); \
        *(float4*)&Bs[B][kB0][nB0] = u;                                            \
        u.x = tf32r(rb1.x); u.y = tf32r(rb1.y); u.z = tf32r(rb1.z); u.w = tf32r(rb1.w); \
        *(float4*)&Bs[B][kB1][nB1] = u;                                            \
    }

    LOAD_REGS(0);
    STORE_BUF(0);
    __syncthreads();

    int cur = 0;
#pragma unroll
    for (int it = 0; it < 8; it++) {
        if (it < 7) LOAD_REGS((it + 1) * 16);
        // compute 2 k-steps from buffer cur
#pragma unroll
        for (int kk = 0; kk < 16; kk += 8) {
            uint32_t a[2][4], b[8][2];
#pragma unroll
            for (int mt = 0; mt < 2; mt++) {
                int r = warp_m * 32 + mt * 16 + g;
                a[mt][0] = __float_as_uint(Am[cur][r][kk + t]);
                a[mt][1] = __float_as_uint(Am[cur][r + 8][kk + t]);
                a[mt][2] = __float_as_uint(Am[cur][r][kk + t + 4]);
                a[mt][3] = __float_as_uint(Am[cur][r + 8][kk + t + 4]);
            }
#pragma unroll
            for (int nt = 0; nt < 8; nt++) {
                int cn = warp_n * 64 + nt * 8 + g;
                b[nt][0] = __float_as_uint(Bs[cur][kk + t][cn]);
                b[nt][1] = __float_as_uint(Bs[cur][kk + t + 4][cn]);
            }
#pragma unroll
            for (int mt = 0; mt < 2; mt++)
#pragma unroll
                for (int nt = 0; nt < 8; nt++) {
                    asm volatile(
                        "mma.sync.aligned.m16n8k8.row.col.f32.tf32.tf32.f32 "
                        "{%0,%1,%2,%3},{%4,%5,%6,%7},{%8,%9},{%0,%1,%2,%3};"
                        : "+f"(c[mt][nt][0]), "+f"(c[mt][nt][1]),
                          "+f"(c[mt][nt][2]), "+f"(c[mt][nt][3])
                        : "r"(a[mt][0]), "r"(a[mt][1]), "r"(a[mt][2]), "r"(a[mt][3]),
                          "r"(b[nt][0]), "r"(b[nt][1]));
                }
        }
        if (it < 7) {
            STORE_BUF(cur ^ 1);
            __syncthreads();
            cur ^= 1;
        }
    }
#undef LOAD_REGS
#undef STORE_BUF

    // epilogue: c0,c1 -> (row g, cols 2t,2t+1); c2,c3 -> (row g+8)
#pragma unroll
    for (int nt = 0; nt < 8; nt++) {
        int col = warp_n * 64 + nt * 8 + t * 2;
        float2 bb = *(const float2*)(bias + col);
#pragma unroll
        for (int mt = 0; mt < 2; mt++) {
            int r0 = bm + warp_m * 32 + mt * 16 + g;
            if (r0 < M) {
                float2 o = make_float2(c[mt][nt][0] + bb.x, c[mt][nt][1] + bb.y);
                *(float2*)(Y + (size_t)r0 * 128 + col) = o;
            }
            int r1 = r0 + 8;
            if (r1 < M) {
                float2 o = make_float2(c[mt][nt][2] + bb.x, c[mt][nt][3] + bb.y);
                *(float2*)(Y + (size_t)r1 * 128 + col) = o;
            }
        }
    }
}

// ---------------- CSR gather-reduce, 128-wide: warp per dst node -------------
__global__ void reduce128(int which) {
    const float4* Wh = (which == 0) ? g_Wh_uu : (which == 1) ? g_Wh_iu : g_Wh_ui;
    float4* acc = (which == 0) ? g_acc_uu : (which == 1) ? g_acc_iu : g_acc_ui;
    int w = (blockIdx.x * blockDim.x + threadIdx.x) >> 5;
    int lane = threadIdx.x & 31;
    if (w >= 100000) return;
    int off = which * 100000;
    int beg = g_rowstart[off + w];
    int end = g_rowstart[off + w + 1];
    float4 s = make_float4(0.f, 0.f, 0.f, 0.f);
    for (int j = beg; j < end; j++) {
        int sc = g_slot[j];
        float4 v = Wh[(size_t)sc * 32 + lane];
        s.x += v.x; s.y += v.y; s.z += v.z; s.w += v.w;
    }
    acc[(size_t)w * 32 + lane] = s;
}

// ---------------- skinny GEMM with fused layer-0 mean+relu epilogue ---------
__global__ void gemm16(const float* __restrict__ W, const float* __restrict__ b,
                       int M, int which) {
    float* Y = (which == 0) ? (float*)g_Wh1_uu : (float*)g_Wh1_iu;
    __shared__ float Xs[64][130];
    __shared__ float Ws[128 * 16];
    __shared__ float bs[16];
    int tid = threadIdx.x;
    int base = blockIdx.x * 64;
#pragma unroll
    for (int i = 0; i < 8; i++) Ws[tid + i * 256] = W[tid + i * 256];
    if (tid < 16) bs[tid] = b[tid];
#pragma unroll
    for (int i = 0; i < 8; i++) {
        int f = tid + i * 256;
        int r = f >> 5, c4 = f & 31;
        int row = base + r;
        float4 v = make_float4(0.f, 0.f, 0.f, 0.f);
        if (row < M) {
            if (which == 0) {
                float iu = 1.f / fmaxf((float)g_deg[row], 1.f);
                float ii = 1.f / fmaxf((float)g_deg[100000 + row], 1.f);
                float4 a = g_acc_uu[(size_t)row * 32 + c4];
                float4 c = g_acc_iu[(size_t)row * 32 + c4];
                v.x = fmaxf(a.x * iu + c.x * ii, 0.f);
                v.y = fmaxf(a.y * iu + c.y * ii, 0.f);
                v.z = fmaxf(a.z * iu + c.z * ii, 0.f);
                v.w = fmaxf(a.w * iu + c.w * ii, 0.f);
            } else {
                float inv = 1.f / fmaxf((float)g_deg[200000 + row], 1.f);
                float4 a = g_acc_ui[(size_t)row * 32 + c4];
                v.x = fmaxf(a.x * inv, 0.f);
                v.y = fmaxf(a.y * inv, 0.f);
                v.z = fmaxf(a.z * inv, 0.f);
                v.w = fmaxf(a.w * inv, 0.f);
            }
        }
        Xs[r][c4 * 4 + 0] = v.x; Xs[r][c4 * 4 + 1] = v.y;
        Xs[r][c4 * 4 + 2] = v.z; Xs[r][c4 * 4 + 3] = v.w;
    }
    __syncthreads();
    int r = tid >> 2, cb = (tid & 3) * 4;
    float4 acc = make_float4(0.f, 0.f, 0.f, 0.f);
#pragma unroll 8
    for (int k = 0; k < 128; k++) {
        float x = Xs[r][k];
        float4 w = *(float4*)&Ws[k * 16 + cb];
        acc.x = fmaf(x, w.x, acc.x);
        acc.y = fmaf(x, w.y, acc.y);
        acc.z = fmaf(x, w.z, acc.z);
        acc.w = fmaf(x, w.w, acc.w);
    }
    int row = base + r;
    if (row < M) {
        float4 o;
        o.x = acc.x + bs[cb + 0];
        o.y = acc.y + bs[cb + 1];
        o.z = acc.z + bs[cb + 2];
        o.w = acc.w + bs[cb + 3];
        *(float4*)(Y + (size_t)row * 16 + cb) = o;
    }
}

// ---------------- CSR gather-reduce, 16-wide: 4 lanes per dst node ----------
__global__ void reduce16(int which) {
    const float4* Wh = (which == 0) ? g_Wh1_uu : g_Wh1_iu;
    float4* acc = (which == 0) ? g_acc1_uu : g_acc1_iu;
    int id = blockIdx.x * blockDim.x + threadIdx.x;
    int n = id >> 2, part = id & 3;
    if (n >= 100000) return;
    int off = which * 100000;                 // etype 0 = uu, 1 = iu
    int beg = g_rowstart[off + n];
    int end = g_rowstart[off + n + 1];
    float4 s = make_float4(0.f, 0.f, 0.f, 0.f);
    for (int j = beg; j < end; j++) {
        int sc = g_slot[j];
        float4 v = Wh[(size_t)sc * 4 + part];
        s.x += v.x; s.y += v.y; s.z += v.z; s.w += v.w;
    }
    acc[(size_t)n * 4 + part] = s;
}

// ---------------- final combine: mean + mean (no relu) ----------------
__global__ void final_out(float4* __restrict__ out) {
    int i = blockIdx.x * blockDim.x + threadIdx.x;
    if (i >= NUSER * 4) return;
    int node = i >> 2;
    float iu = 1.f / fmaxf((float)g_deg[node], 1.f);
    float ii = 1.f / fmaxf((float)g_deg[100000 + node], 1.f);
    float4 a = g_acc1_uu[i], c = g_acc1_iu[i];
    float4 o;
    o.x = a.x * iu + c.x * ii;
    o.y = a.y * iu + c.y * ii;
    o.z = a.z * iu + c.z * ii;
    o.w = a.w * iu + c.w * ii;
    out[i] = o;
}

// ---------------- launch ----------------
extern "C" void kernel_launch(void* const* d_in, const int* in_sizes, int n_in,
                              void* d_out, int out_size) {
    const float* embed_user = (const float*)d_in[0];
    const float* embed_item = (const float*)d_in[1];
    const int* src_uu = (const int*)d_in[2];
    const int* dst_uu = (const int*)d_in[3];
    const int* src_ui = (const int*)d_in[4];
    const int* dst_ui = (const int*)d_in[5];
    const int* src_iu = (const int*)d_in[6];
    const int* dst_iu = (const int*)d_in[7];
    const float* W0_uu = (const float*)d_in[8];
    const float* b0_uu = (const float*)d_in[9];
    const float* W0_ui = (const float*)d_in[10];
    const float* b0_ui = (const float*)d_in[11];
    const float* W0_iu = (const float*)d_in[12];
    const float* b0_iu = (const float*)d_in[13];
    const float* W1_uu = (const float*)d_in[14];
    const float* b1_uu = (const float*)d_in[15];
    const float* W1_iu = (const float*)d_in[18];
    const float* b1_iu = (const float*)d_in[19];

    const int eblk = (NE + 255) / 256;
    const int nscan = (NTOT + 1023) / 1024;  // 293

    // ---- CSR build (shared by both layers) ----
    zero_deg<<<(NTOT + 255) / 256, 256>>>();
    hist_k<<<eblk, 256>>>(dst_uu, 0);
    hist_k<<<eblk, 256>>>(dst_iu, 100000);
    hist_k<<<eblk, 256>>>(dst_ui, 200000);
    scan_k1<<<nscan, 1024>>>();
    scan_k2<<<1, 512>>>(nscan);
    scan_k3<<<nscan, 1024>>>();
    fill_k<<<eblk, 256>>>(src_uu, dst_uu, 0);
    fill_k<<<eblk, 256>>>(src_iu, dst_iu, 100000);
    fill_k<<<eblk, 256>>>(src_ui, dst_ui, 200000);

    // ---- layer 0: project (tf32 mma) then reduce while Wh is L2-hot ----
    gemm128<<<(NUSER + 127) / 128, 256>>>(embed_user, W0_uu, b0_uu, NUSER, 0);
    reduce128<<<(NUSER * 32 + 255) / 256, 256>>>(0);
    gemm128<<<(NITEM + 127) / 128, 256>>>(embed_item, W0_iu, b0_iu, NITEM, 2);
    reduce128<<<(NUSER * 32 + 255) / 256, 256>>>(1);
    gemm128<<<(NUSER + 127) / 128, 256>>>(embed_user, W0_ui, b0_ui, NUSER, 1);
    reduce128<<<(NITEM * 32 + 255) / 256, 256>>>(2);

    // ---- layer 1: skinny GEMM (mean+relu fused), CSR reduce ----
    gemm16<<<(NUSER + 63) / 64, 256>>>(W1_uu, b1_uu, NUSER, 0);
    gemm16<<<(NITEM + 63) / 64, 256>>>(W1_iu, b1_iu, NITEM, 1);
    reduce16<<<(NUSER * 4 + 255) / 256, 256>>>(0);
    reduce16<<<(NUSER * 4 + 255) / 256, 256>>>(1);

    // ---- output ----
    final_out<<<(NUSER * 4 + 255) / 256, 256>>>((float4*)d_out);
}